// round 1
// baseline (speedup 1.0000x reference)
#include <cuda_runtime.h>
#include <cstdint>

// Problem constants
// P=8, B=4, C=32, H=256, W=256, M1=M2=32
// rows R = P*B*C*H = 262144 ; pbc batches = P*B*C = 1024

#define R_ROWS (262144)
#define NBATCH (1024)

// ---------------- scratch ----------------
__device__ __align__(16) float g_Y [R_ROWS * 64];   // fwd-W output: [pbc*256+h][2y+p]
__device__ __align__(16) float g_V [R_ROWS * 64];   // inv-H output: [pbc*256+h][2y+p]
__device__ __align__(16) float g_Z [NBATCH * 64 * 64]; // fwd-H out: [(pbc*64+j)][2y+p]
__device__ __align__(16) float g_Z3[NBATCH * 64 * 64]; // mix out  : same layout
__device__ __align__(16) float g_T1 [256 * 64];     // [w][2k+p] : cos, -sin of 2pi w k/256
__device__ __align__(16) float g_T2re[64 * 256];    // [j][h]    : cos(2pi xr(j) h/256)
__device__ __align__(16) float g_T2im[64 * 256];    // [j][h]    : -sin(...)
__device__ __align__(16) float g_T5 [64 * 256];     // [2k+p][w] : c_k cos /65536, -c_k sin /65536

// ---------------- twiddle init (recomputed every launch; deterministic) ----------------
__global__ void init_twiddles() {
    int t = blockIdx.x * blockDim.x + threadIdx.x;
    // T1: 256*32 entries
    if (t < 256 * 32) {
        int w = t >> 5, k = t & 31;
        int m = (w * k) & 255;
        double s, c;
        sincospi(2.0 * m / 256.0, &s, &c);
        g_T1[w * 64 + 2 * k]     = (float)c;
        g_T1[w * 64 + 2 * k + 1] = (float)(-s);
    }
    // T2: 64*256 entries
    if (t < 64 * 256) {
        int j = t >> 8, h = t & 255;
        int xr = (j < 32) ? j : (192 + j);
        int m = (xr * h) & 255;
        double s, c;
        sincospi(2.0 * m / 256.0, &s, &c);
        g_T2re[j * 256 + h] = (float)c;
        g_T2im[j * 256 + h] = (float)(-s);
    }
    // T5: 32*256 entries (fills both q=2k and q=2k+1 rows)
    if (t < 32 * 256) {
        int k = t >> 8, w = t & 255;
        int m = (k * w) & 255;
        double s, c;
        sincospi(2.0 * m / 256.0, &s, &c);
        double coef = ((k == 0) ? 1.0 : 2.0) / 65536.0;
        g_T5[(2 * k) * 256 + w]     = (float)(coef * c);
        g_T5[(2 * k + 1) * 256 + w] = (float)(-coef * s);
    }
}

// ---------------- generic row-major SGEMM: C[M,N] = A[M,K]*B[K,N] ----------------
// BM=128, BN=64, BK=32, thread tile 8x4, 256 threads. grid=(M/128, N/64)
__global__ void sgemm128x64(const float* __restrict__ A, const float* __restrict__ B,
                            float* __restrict__ C, int K, int N) {
    __shared__ float As[32][128];
    __shared__ float Bs[32][64];
    const int t = threadIdx.x;
    const int tx = t & 15;          // col group (4 cols)
    const int ty = t >> 4;          // row group (8 rows)
    const int rowBase = blockIdx.x * 128;
    const int colBase = blockIdx.y * 64;

    float acc[8][4];
#pragma unroll
    for (int i = 0; i < 8; ++i)
#pragma unroll
        for (int j = 0; j < 4; ++j) acc[i][j] = 0.f;

    for (int k0 = 0; k0 < K; k0 += 32) {
        // load A tile 128x32 (transposed into As)
        {
            int r = t >> 3, kq = t & 7;
#pragma unroll
            for (int pass = 0; pass < 4; ++pass) {
                int row = r + pass * 32;
                float4 v = *reinterpret_cast<const float4*>(
                    &A[(size_t)(rowBase + row) * K + k0 + kq * 4]);
                As[kq * 4 + 0][row] = v.x;
                As[kq * 4 + 1][row] = v.y;
                As[kq * 4 + 2][row] = v.z;
                As[kq * 4 + 3][row] = v.w;
            }
        }
        // load B tile 32x64
        {
            int r = t >> 4, cq = t & 15;
#pragma unroll
            for (int pass = 0; pass < 2; ++pass) {
                int row = r + pass * 16;
                float4 v = *reinterpret_cast<const float4*>(
                    &B[(size_t)(k0 + row) * N + colBase + cq * 4]);
                *reinterpret_cast<float4*>(&Bs[row][cq * 4]) = v;
            }
        }
        __syncthreads();
#pragma unroll
        for (int kk = 0; kk < 32; ++kk) {
            float a[8], b[4];
            *reinterpret_cast<float4*>(&a[0]) = *reinterpret_cast<float4*>(&As[kk][ty * 8]);
            *reinterpret_cast<float4*>(&a[4]) = *reinterpret_cast<float4*>(&As[kk][ty * 8 + 4]);
            *reinterpret_cast<float4*>(&b[0]) = *reinterpret_cast<float4*>(&Bs[kk][tx * 4]);
#pragma unroll
            for (int i = 0; i < 8; ++i)
#pragma unroll
                for (int j = 0; j < 4; ++j) acc[i][j] += a[i] * b[j];
        }
        __syncthreads();
    }
#pragma unroll
    for (int i = 0; i < 8; ++i) {
        float4 v = make_float4(acc[i][0], acc[i][1], acc[i][2], acc[i][3]);
        *reinterpret_cast<float4*>(
            &C[(size_t)(rowBase + ty * 8 + i) * N + colBase + tx * 4]) = v;
    }
}

// ---------------- forward H DFT (batched complex) ----------------
// Z[pbc][j][y] = sum_h T2[j][h] * Y[pbc][h][y]   (complex)
__global__ void fwd_h(const float* __restrict__ Y, float* __restrict__ Z) {
    __shared__ float Ysre[32][32], Ysim[32][32];
    __shared__ float Tsre[64][32], Tsim[64][32];
    const int t = threadIdx.x;
    const int pbc = blockIdx.x;
    const int y = t & 31, jg = t >> 5;
    float accre[8], accim[8];
#pragma unroll
    for (int jj = 0; jj < 8; ++jj) { accre[jj] = 0.f; accim[jj] = 0.f; }

    for (int h0 = 0; h0 < 256; h0 += 32) {
#pragma unroll
        for (int it = 0; it < 8; ++it) {
            int idx = t + it * 256;
            int hl = idx >> 6, rem = idx & 63;
            float v = Y[((size_t)pbc * 256 + h0 + hl) * 64 + rem];
            if (rem & 1) Ysim[hl][rem >> 1] = v;
            else         Ysre[hl][rem >> 1] = v;
        }
#pragma unroll
        for (int it = 0; it < 8; ++it) {
            int idx = t + it * 256;
            int j = idx >> 5, hh = idx & 31;
            Tsre[j][hh] = g_T2re[j * 256 + h0 + hh];
            Tsim[j][hh] = g_T2im[j * 256 + h0 + hh];
        }
        __syncthreads();
        for (int hh = 0; hh < 32; ++hh) {
            float yre = Ysre[hh][y], yim = Ysim[hh][y];
#pragma unroll
            for (int jj = 0; jj < 8; ++jj) {
                float tre = Tsre[jg * 8 + jj][hh];
                float tim = Tsim[jg * 8 + jj][hh];
                accre[jj] += tre * yre - tim * yim;
                accim[jj] += tre * yim + tim * yre;
            }
        }
        __syncthreads();
    }
#pragma unroll
    for (int jj = 0; jj < 8; ++jj) {
        int j = jg * 8 + jj;
        Z[((size_t)pbc * 64 + j) * 64 + 2 * y]     = accre[jj];
        Z[((size_t)pbc * 64 + j) * 64 + 2 * y + 1] = accim[jj];
    }
}

// ---------------- channel mix ----------------
// Z3[p,b,o,j,y] = sum_i Z[p,b,i,j,y] * w[i,o,p,x,y]  (complex; w1 for j<32, w4 else)
__global__ void chanmix(const float* __restrict__ Z,
                        const float* __restrict__ w1re, const float* __restrict__ w1im,
                        const float* __restrict__ w4re, const float* __restrict__ w4im,
                        float* __restrict__ Z3) {
    __shared__ float Zsre[4][32][32], Zsim[4][32][32];
    __shared__ float Wsre[32][32], Wsim[32][32];
    const int t = threadIdx.x;       // 128 threads
    const int p = blockIdx.x >> 6;
    const int j = blockIdx.x & 63;
    const int x = j & 31;
    const float* wre = (j < 32) ? w1re : w4re;
    const float* wim = (j < 32) ? w1im : w4im;
    const int y = t & 31, bb = t >> 5;

    for (int it = 0; it < 64; ++it) {
        int idx = t + it * 128;
        int pair = idx >> 6, rem = idx & 63;
        int b = pair >> 5, i = pair & 31;
        float v = Z[((size_t)((p * 4 + b) * 32 + i) * 64 + j) * 64 + rem];
        if (rem & 1) Zsim[b][i][rem >> 1] = v;
        else         Zsre[b][i][rem >> 1] = v;
    }
    __syncthreads();

    for (int o = 0; o < 32; ++o) {
#pragma unroll
        for (int it = 0; it < 8; ++it) {
            int idx = t + it * 128;
            int i = idx >> 5, yy = idx & 31;
            size_t widx = ((((size_t)(i * 32 + o)) * 8 + p) * 32 + x) * 32 + yy;
            Wsre[i][yy] = wre[widx];
            Wsim[i][yy] = wim[widx];
        }
        __syncthreads();
        float accre = 0.f, accim = 0.f;
#pragma unroll
        for (int i = 0; i < 32; ++i) {
            float zre = Zsre[bb][i][y], zim = Zsim[bb][i][y];
            float wr = Wsre[i][y], wi = Wsim[i][y];
            accre += zre * wr - zim * wi;
            accim += zre * wi + zim * wr;
        }
        size_t obase = ((size_t)((p * 4 + bb) * 32 + o) * 64 + j) * 64;
        Z3[obase + 2 * y]     = accre;
        Z3[obase + 2 * y + 1] = accim;
        __syncthreads();
    }
}

// ---------------- inverse H DFT (batched complex, conj twiddles) ----------------
// V[pbc][h][y] = sum_j conj(T2[j][h]) * Z3[pbc][j][y]
__global__ void inv_h(const float* __restrict__ Z3, float* __restrict__ V) {
    __shared__ float Zsre[16][32], Zsim[16][32];
    __shared__ float Tsre[16][64], Tsim[16][64];
    const int t = threadIdx.x;
    const int pbc = blockIdx.x;
    const int hb = blockIdx.y;       // 0..3, 64 h per block
    const int y = t & 31, hg = t >> 5;
    float accre[8], accim[8];
#pragma unroll
    for (int i = 0; i < 8; ++i) { accre[i] = 0.f; accim[i] = 0.f; }

    for (int j0 = 0; j0 < 64; j0 += 16) {
#pragma unroll
        for (int it = 0; it < 4; ++it) {
            int idx = t + it * 256;
            int jl = idx >> 6, rem = idx & 63;
            float v = Z3[((size_t)pbc * 64 + j0 + jl) * 64 + rem];
            if (rem & 1) Zsim[jl][rem >> 1] = v;
            else         Zsre[jl][rem >> 1] = v;
        }
#pragma unroll
        for (int it = 0; it < 4; ++it) {
            int idx = t + it * 256;
            int jl = idx >> 6, hh = idx & 63;
            Tsre[jl][hh] = g_T2re[(j0 + jl) * 256 + hb * 64 + hh];
            Tsim[jl][hh] = g_T2im[(j0 + jl) * 256 + hb * 64 + hh];
        }
        __syncthreads();
        for (int jl = 0; jl < 16; ++jl) {
            float zre = Zsre[jl][y], zim = Zsim[jl][y];
#pragma unroll
            for (int i = 0; i < 8; ++i) {
                float tre = Tsre[jl][hg * 8 + i];
                float tim = Tsim[jl][hg * 8 + i];
                accre[i] += tre * zre + tim * zim;   // z * conj(T2)
                accim[i] += tre * zim - tim * zre;
            }
        }
        __syncthreads();
    }
#pragma unroll
    for (int i = 0; i < 8; ++i) {
        size_t row = (size_t)pbc * 256 + hb * 64 + hg * 8 + i;
        V[row * 64 + 2 * y]     = accre[i];
        V[row * 64 + 2 * y + 1] = accim[i];
    }
}

// ---------------- launch ----------------
extern "C" void kernel_launch(void* const* d_in, const int* in_sizes, int n_in,
                              void* d_out, int out_size) {
    const float* x    = (const float*)d_in[0];
    const float* w1re = (const float*)d_in[1];
    const float* w1im = (const float*)d_in[2];
    const float* w4re = (const float*)d_in[3];
    const float* w4im = (const float*)d_in[4];
    float* out = (float*)d_out;

    void *pY, *pV, *pZ, *pZ3, *pT1, *pT5;
    cudaGetSymbolAddress(&pY,  g_Y);
    cudaGetSymbolAddress(&pV,  g_V);
    cudaGetSymbolAddress(&pZ,  g_Z);
    cudaGetSymbolAddress(&pZ3, g_Z3);
    cudaGetSymbolAddress(&pT1, g_T1);
    cudaGetSymbolAddress(&pT5, g_T5);

    init_twiddles<<<64, 256>>>();

    // S1: fwd W DFT  — Y = x(262144x256) * T1(256x64)
    sgemm128x64<<<dim3(R_ROWS / 128, 1), 256>>>(x, (const float*)pT1, (float*)pY, 256, 64);

    // S2: fwd H DFT (batched complex)
    fwd_h<<<NBATCH, 256>>>((const float*)pY, (float*)pZ);

    // S3: channel mixing
    chanmix<<<512, 128>>>((const float*)pZ, w1re, w1im, w4re, w4im, (float*)pZ3);

    // S4: inv H DFT (batched complex)
    inv_h<<<dim3(NBATCH, 4), 256>>>((const float*)pZ3, (float*)pV);

    // S5: inv W DFT — out = V(262144x64) * T5(64x256)
    sgemm128x64<<<dim3(R_ROWS / 128, 4), 256>>>((const float*)pV, (const float*)pT5, out, 64, 256);
}

// round 2
// speedup vs baseline: 1.1935x; 1.1935x over previous
#include <cuda_runtime.h>
#include <cstdint>

// P=8, B=4, C=32, H=256, W=256, M1=M2=32
// rows R = P*B*C*H = 262144 ; pbc = P*B*C = 1024 ; cols (pbc,y) = 32768

// ---------------- scratch (split re/im planes) ----------------
__device__ __align__(16) float g_Y [2u * 256 * 32768];   // [plane][h][pbc*32+y]
__device__ __align__(16) float g_Z [128u * 32768];       // [plane*64+j][pbc*32+y]
__device__ __align__(16) float g_Z3[128u * 32768];       // same layout
__device__ __align__(16) float g_V [262144u * 64];       // [(pbc*256+h)][plane*32+y]
__device__ __align__(16) float g_T1[256 * 64];           // [w][c]: c<32 cos, c>=32 -sin
__device__ __align__(16) float g_A2[128 * 512];          // fwd-H complex->real block matrix
__device__ __align__(16) float g_A4[512 * 128];          // inv-H complex->real block matrix
__device__ __align__(16) float g_T5[64 * 256];           // [k|32+k][w]: c_k cos /65536, -c_k sin /65536

// ---------------- table init ----------------
__global__ void init_tables() {
    int t = blockIdx.x * 256 + threadIdx.x;   // 0..65535
    // T1: 256x64
    if (t < 256 * 64) {
        int w = t >> 6, c = t & 63, y = c & 31;
        int m = (w * y) & 255;
        double s, ct; sincospi(2.0 * m / 256.0, &s, &ct);
        g_T1[t] = (c < 32) ? (float)ct : (float)(-s);
    }
    // A2: 128x512.  Zre = cos*Yre + sin*Yim ; Zim = -sin*Yre + cos*Yim  (T2 = e^{-i th})
    {
        int r = t >> 9, k = t & 511;
        int pk = k >> 8, h = k & 255;
        int j = r & 63;
        int xr = (j < 32) ? j : (192 + j);
        int m = (xr * h) & 255;
        double s, ct; sincospi(2.0 * m / 256.0, &s, &ct);
        float v;
        if (r < 64) v = (pk == 0) ? (float)ct : (float)s;
        else        v = (pk == 0) ? (float)(-s) : (float)ct;
        g_A2[t] = v;
    }
    // A4: 512x128.  Vre = cos*Zre - sin*Zim ; Vim = sin*Zre + cos*Zim  (conj twiddle)
    {
        int r = t >> 7, c = t & 127;
        int pr = r >> 8, h = r & 255;
        int pc = c >> 6, j = c & 63;
        int xr = (j < 32) ? j : (192 + j);
        int m = (xr * h) & 255;
        double s, ct; sincospi(2.0 * m / 256.0, &s, &ct);
        float v;
        if (pr == 0) v = (pc == 0) ? (float)ct : (float)(-s);
        else         v = (pc == 0) ? (float)s  : (float)ct;
        g_A4[t] = v;
    }
    // T5: 64x256
    if (t < 64 * 256) {
        int r = t >> 8, w = t & 255, k = r & 31;
        int m = (k * w) & 255;
        double s, ct; sincospi(2.0 * m / 256.0, &s, &ct);
        double coef = ((k == 0) ? 1.0 : 2.0) / 65536.0;
        g_T5[t] = (r < 32) ? (float)(coef * ct) : (float)(-coef * s);
    }
}

// ---------------- templated SGEMM: C = A(MxK) * B(KxN), row-major ----------------
// 256 threads, TM x TN = 8x8 microtile, global->register prefetch.
// MODE 0: plain row-major C
// MODE 1: S1 epilogue -> Y planes  [plane][h][pbc*32+y]   (M=262144 rows = pbc*256+h, N=64 cols = plane*32+y)
// MODE 2: S4 epilogue -> V         [(pbc*256+h)][plane*32+y] (M=512 rows = plane*256+h, N=32768 cols = pbc*32+y)
template<int BM, int BN, int BK, int TM, int TN, long M, long N, long K, int MODE>
__global__ void __launch_bounds__(256) sgemm(const float* __restrict__ A,
                                             const float* __restrict__ B,
                                             float* __restrict__ C) {
    constexpr int TX = BN / TN;
    constexpr int TY = BM / TM;
    static_assert(TX * TY == 256, "thread layout");
    constexpr int AF = BM * BK / 1024;   // float4s per thread for A tile
    constexpr int BF = BN * BK / 1024;
    __shared__ float As[BK][BM + 4];
    __shared__ float Bs[BK][BN];

    const int t = threadIdx.x;
    const int tx = t % TX, ty = t / TX;
    const long rowBase = (long)blockIdx.x * BM;
    const long colBase = (long)blockIdx.y * BN;

    float4 aReg[AF], bReg[BF];
    float acc[TM][TN];
#pragma unroll
    for (int i = 0; i < TM; ++i)
#pragma unroll
        for (int j = 0; j < TN; ++j) acc[i][j] = 0.f;

    auto loadG = [&](long k0) {
#pragma unroll
        for (int f4 = 0; f4 < AF; ++f4) {
            int f = t + f4 * 256;
            int ar = f / (BK / 4), ac = f % (BK / 4);
            aReg[f4] = *reinterpret_cast<const float4*>(&A[(rowBase + ar) * K + k0 + ac * 4]);
        }
#pragma unroll
        for (int f4 = 0; f4 < BF; ++f4) {
            int f = t + f4 * 256;
            int br = f / (BN / 4), bc = f % (BN / 4);
            bReg[f4] = *reinterpret_cast<const float4*>(&B[(k0 + br) * N + colBase + bc * 4]);
        }
    };
    auto storeS = [&]() {
#pragma unroll
        for (int f4 = 0; f4 < AF; ++f4) {
            int f = t + f4 * 256;
            int ar = f / (BK / 4), ac = f % (BK / 4);
            As[ac * 4 + 0][ar] = aReg[f4].x;
            As[ac * 4 + 1][ar] = aReg[f4].y;
            As[ac * 4 + 2][ar] = aReg[f4].z;
            As[ac * 4 + 3][ar] = aReg[f4].w;
        }
#pragma unroll
        for (int f4 = 0; f4 < BF; ++f4) {
            int f = t + f4 * 256;
            int br = f / (BN / 4), bc = f % (BN / 4);
            *reinterpret_cast<float4*>(&Bs[br][bc * 4]) = bReg[f4];
        }
    };
    auto compute = [&]() {
#pragma unroll
        for (int kk = 0; kk < BK; ++kk) {
            float a[TM], b[TN];
#pragma unroll
            for (int q = 0; q < TM; q += 4)
                *reinterpret_cast<float4*>(&a[q]) =
                    *reinterpret_cast<const float4*>(&As[kk][ty * TM + q]);
#pragma unroll
            for (int q = 0; q < TN; q += 4)
                *reinterpret_cast<float4*>(&b[q]) =
                    *reinterpret_cast<const float4*>(&Bs[kk][tx * TN + q]);
#pragma unroll
            for (int i = 0; i < TM; ++i)
#pragma unroll
                for (int j = 0; j < TN; ++j) acc[i][j] += a[i] * b[j];
        }
    };

    loadG(0);
    storeS();
    __syncthreads();
    constexpr long KT = K / BK;
#pragma unroll 1
    for (long kt = 1; kt < KT; ++kt) {
        loadG(kt * BK);       // prefetch next tile into registers
        compute();            // compute on current smem tile
        __syncthreads();
        storeS();
        __syncthreads();
    }
    compute();

    // epilogue
#pragma unroll
    for (int i = 0; i < TM; ++i) {
        long r = rowBase + ty * TM + i;
#pragma unroll
        for (int jj = 0; jj < TN; jj += 4) {
            long c = colBase + tx * TN + jj;
            float4 v = make_float4(acc[i][jj], acc[i][jj + 1], acc[i][jj + 2], acc[i][jj + 3]);
            long addr;
            if (MODE == 0) {
                addr = r * N + c;
            } else if (MODE == 1) {
                long plane = c >> 5, y = c & 31;
                addr = plane * 8388608L + (r & 255) * 32768L + (r >> 8) * 32 + y;
            } else {
                long plane = r >> 8, h = r & 255, pbc = c >> 5, y = c & 31;
                addr = (pbc * 256 + h) * 64 + plane * 32 + y;
            }
            *reinterpret_cast<float4*>(&C[addr]) = v;
        }
    }
}

// ---------------- channel mix (plane layout) ----------------
// Z3[plane'][j][p,b,o,y] = complex mix over i of Z[plane][j][p,b,i,y] with w(i,o,p,x=j&31,y)
__global__ void __launch_bounds__(256) chanmix(const float* __restrict__ Z,
                                               const float* __restrict__ w1re,
                                               const float* __restrict__ w1im,
                                               const float* __restrict__ w4re,
                                               const float* __restrict__ w4im,
                                               float* __restrict__ Z3) {
    __shared__ float Zs[2][4][32][32];   // plane, b, i, y   (32KB)
    __shared__ float Ws[2][2][32][32];   // o_half, plane, i, y (16KB)
    const int t = threadIdx.x;
    const int p = blockIdx.x >> 6;
    const int j = blockIdx.x & 63;
    const int x = j & 31;
    const float* wre = (j < 32) ? w1re : w4re;
    const float* wim = (j < 32) ? w1im : w4im;

    // load Z tiles: 2048 float4
#pragma unroll
    for (int pass = 0; pass < 8; ++pass) {
        int f = t + pass * 256;
        int plane = f >> 10;
        int rem = f & 1023;
        int bi = rem >> 3;      // 0..127 = b*32+i
        int y4 = rem & 7;
        float4 v = *reinterpret_cast<const float4*>(
            &Z[(size_t)(plane * 64 + j) * 32768 + (size_t)(p * 128 + bi) * 32 + y4 * 4]);
        *reinterpret_cast<float4*>(&Zs[plane][bi >> 5][bi & 31][y4 * 4]) = v;
    }
    __syncthreads();

    const int o_l = t >> 7;
    const int bb  = (t >> 5) & 3;
    const int y   = t & 31;

    for (int o0 = 0; o0 < 32; o0 += 2) {
        // load W for (o0, o0+1): 1024 float4
#pragma unroll
        for (int pass = 0; pass < 4; ++pass) {
            int f = t + pass * 256;
            int ol = f >> 9;
            int plane = (f >> 8) & 1;
            int i = (f >> 3) & 31;
            int y4 = f & 7;
            const float* wp = plane ? wim : wre;
            float4 v = *reinterpret_cast<const float4*>(
                &wp[((((size_t)(i * 32 + o0 + ol)) * 8 + p) * 32 + x) * 32 + y4 * 4]);
            *reinterpret_cast<float4*>(&Ws[ol][plane][i][y4 * 4]) = v;
        }
        __syncthreads();
        float accre = 0.f, accim = 0.f;
#pragma unroll
        for (int i = 0; i < 32; ++i) {
            float zre = Zs[0][bb][i][y], zim = Zs[1][bb][i][y];
            float wr  = Ws[o_l][0][i][y], wi = Ws[o_l][1][i][y];
            accre += zre * wr - zim * wi;
            accim += zre * wi + zim * wr;
        }
        int o = o0 + o_l;
        size_t col = (size_t)(p * 128 + bb * 32 + o) * 32 + y;
        Z3[(size_t)j * 32768 + col]          = accre;
        Z3[(size_t)(64 + j) * 32768 + col]   = accim;
        __syncthreads();
    }
}

// ---------------- launch ----------------
extern "C" void kernel_launch(void* const* d_in, const int* in_sizes, int n_in,
                              void* d_out, int out_size) {
    const float* x    = (const float*)d_in[0];
    const float* w1re = (const float*)d_in[1];
    const float* w1im = (const float*)d_in[2];
    const float* w4re = (const float*)d_in[3];
    const float* w4im = (const float*)d_in[4];
    float* out = (float*)d_out;

    void *pY, *pZ, *pZ3, *pV, *pT1, *pA2, *pA4, *pT5;
    cudaGetSymbolAddress(&pY,  g_Y);
    cudaGetSymbolAddress(&pZ,  g_Z);
    cudaGetSymbolAddress(&pZ3, g_Z3);
    cudaGetSymbolAddress(&pV,  g_V);
    cudaGetSymbolAddress(&pT1, g_T1);
    cudaGetSymbolAddress(&pA2, g_A2);
    cudaGetSymbolAddress(&pA4, g_A4);
    cudaGetSymbolAddress(&pT5, g_T5);

    init_tables<<<256, 256>>>();

    // S1: fwd W DFT -> Y planes.  (262144 x 64) = x(262144 x 256) * T1(256 x 64)
    sgemm<256, 64, 16, 8, 8, 262144L, 64L, 256L, 1>
        <<<dim3(1024, 1), 256>>>(x, (const float*)pT1, (float*)pY);

    // S2: fwd H DFT.  Z(128 x 32768) = A2(128 x 512) * Y(512 x 32768)
    sgemm<128, 128, 16, 8, 8, 128L, 32768L, 512L, 0>
        <<<dim3(1, 256), 256>>>((const float*)pA2, (const float*)pY, (float*)pZ);

    // S3: channel mixing
    chanmix<<<512, 256>>>((const float*)pZ, w1re, w1im, w4re, w4im, (float*)pZ3);

    // S4: inv H DFT -> V.  (512 x 32768) = A4(512 x 128) * Z3(128 x 32768)
    sgemm<128, 128, 16, 8, 8, 512L, 32768L, 128L, 2>
        <<<dim3(4, 256), 256>>>((const float*)pA4, (const float*)pZ3, (float*)pV);

    // S5: inv W DFT.  out(262144 x 256) = V(262144 x 64) * T5(64 x 256)
    sgemm<128, 128, 16, 8, 8, 262144L, 256L, 64L, 0>
        <<<dim3(2048, 2), 256>>>((const float*)pV, (const float*)pT5, out);
}